// round 8
// baseline (speedup 1.0000x reference)
#include <cuda_runtime.h>
#include <cstdint>
#include <cstddef>

// Ridge_51178830299316 — rank-2 RLS (Woodbury), row-split across a 2-CTA
// cluster (round 8 = round 7 with the mbarrier.arrive sink-operand fix).
// 64 CTAs = 64 SMs; cluster (2,1,1); batch = blockIdx.x/2.
//
// CTA half h owns M rows [64h, 64h+64) x all 128 cols (8192 elems, 512 P
// threads x 16). P thread: row_g = 64h + (tid>>3), cols cg*16.. (cg=tid&7).
// Per iteration (2 points): apply prev block's rank-2 update fused with two
// matvecs (64 FFMA), butterfly-reduce the 8 col-group partials within each
// 8-lane group (6 shfl), lane cg==0 stores the (p_raw,q_raw) pair for its
// row LOCALLY and REMOTELY (st.shared::cluster to the peer), one lane/warp
// arrives on the peer's mbarrier (release.cluster, sink destination).
// S warp (tid 512..543) is REPLICATED on both CTAs: waits for the peer's 16
// arrivals (acquire.cluster; local half ordered by __syncthreads), then runs
// the identical R3 staleness-correction + 10-value reduce + Woodbury math.
// part2 is 4-deep: with inter-CTA skew <= 1 iteration (enforced by the
// mbar dependency chain), writer (t+1)%4 never collides with a reader.

#define BATCH 32
#define NPTS  256
#define DIM   128
#define HALF  64
#define PTHREADS 512
#define TOT   544
#define NBLK  128

struct SMLayout {
    float  xs[NPTS + 2][DIM];   // full batch data (staged in both CTAs)
    float  ts[NPTS];
    float2 part2[4][DIM];       // (p_raw, q_raw) per row, 4-deep ring
    float  pc[2][DIM];          // column-side p      (written by local S)
    float  vc[2][DIM];          // column-side v
    float  au[2][DIM];          // inv1 * p (row-side)
    float  bu[2][DIM];          // inv2 * v (row-side)
    unsigned long long mbar[4]; // one per part2 slot, arrive count 16
};

__device__ __forceinline__ uint32_t smem_u32(const void* p) {
    uint32_t a;
    asm("{ .reg .u64 t; cvta.to.shared.u64 t, %1; cvt.u32.u64 %0, t; }"
        : "=r"(a) : "l"(p));
    return a;
}
__device__ __forceinline__ void sts_remote_u64(uint32_t laddr, unsigned long long v,
                                               uint32_t peer) {
    asm volatile("{ .reg .u32 ra; mapa.shared::cluster.u32 ra, %0, %2;\n\t"
                 "st.shared::cluster.u64 [ra], %1; }"
                 :: "r"(laddr), "l"(v), "r"(peer) : "memory");
}
__device__ __forceinline__ void mbar_arrive_remote(uint32_t laddr, uint32_t peer) {
    asm volatile("{ .reg .u32 ra;\n\t"
                 "mapa.shared::cluster.u32 ra, %0, %1;\n\t"
                 "mbarrier.arrive.release.cluster.shared::cluster.b64 _, [ra]; }"
                 :: "r"(laddr), "r"(peer) : "memory");
}
__device__ __forceinline__ void mbar_wait_cluster(uint32_t addr, uint32_t parity) {
    asm volatile("{ .reg .pred P;\n\t"
                 "WL%=: mbarrier.try_wait.parity.acquire.cluster.shared::cta.b64 P, [%0], %1, 0x989680;\n\t"
                 "@P bra WD%=;\n\t"
                 "bra WL%=;\n\t"
                 "WD%=: }"
                 :: "r"(addr), "r"(parity) : "memory");
}

__global__ void __launch_bounds__(TOT, 1) __cluster_dims__(2, 1, 1)
ridge_rls_cl_kernel(const float* __restrict__ data,
                    const float* __restrict__ targets,
                    float* __restrict__ out)
{
    extern __shared__ char smem_raw[];
    SMLayout& sm = *reinterpret_cast<SMLayout*>(smem_raw);
    const int tid  = threadIdx.x;
    const int b    = blockIdx.x >> 1;
    const uint32_t half = blockIdx.x & 1;      // == cluster rank (dim.x = 2)
    const uint32_t peer = half ^ 1u;

    // ---- Stage inputs (full copy in both CTAs) ----
    {
        const float4* src = reinterpret_cast<const float4*>(data + (size_t)b * NPTS * DIM);
        float4* dst = reinterpret_cast<float4*>(&sm.xs[0][0]);
        for (int idx = tid; idx < NPTS * DIM / 4; idx += TOT)
            dst[idx] = src[idx];
        if (tid < 2 * DIM / 4)
            reinterpret_cast<float4*>(&sm.xs[NPTS][0])[tid] =
                make_float4(0.f, 0.f, 0.f, 0.f);
        if (tid < NPTS / 4)
            reinterpret_cast<float4*>(sm.ts)[tid] =
                reinterpret_cast<const float4*>(targets + (size_t)b * NPTS)[tid];
    }
    // mbarrier init (before cluster sync)
    if (tid == 0) {
        #pragma unroll
        for (int i = 0; i < 4; i++)
            asm volatile("mbarrier.init.shared.b64 [%0], 16;"
                         :: "r"(smem_u32(&sm.mbar[i])) : "memory");
        asm volatile("fence.mbarrier_init.release.cluster;" ::: "memory");
    }
    __syncthreads();

    // ---- Prologue: raw matvecs of block 0 are I*x_0, I*x_1 (all rows local) ----
    if (tid < DIM) {
        sm.part2[0][tid] = make_float2(sm.xs[0][tid], sm.xs[1][tid]);
        sm.pc[0][tid] = 0.f;  sm.vc[0][tid] = 0.f;   // block -1 update = 0
        sm.au[0][tid] = 0.f;  sm.bu[0][tid] = 0.f;
    }
    if (tid == 0 && half == 0) out[(size_t)b * NPTS] = 0.f;
    __syncthreads();
    // peer's mbarriers must be initialized before our first remote arrive
    asm volatile("barrier.cluster.arrive.aligned;" ::: "memory");
    asm volatile("barrier.cluster.wait.aligned;" ::: "memory");

    // ---- P persistent state: 1 row x 16 cols of this CTA's 64x128 M-half ----
    const int lr    = tid >> 3;              // local row 0..63
    const int row_g = (int)half * HALF + lr; // global row
    const int cg    = tid & 7;               // col group: cols 16cg..16cg+15
    const int c0    = cg * 16;
    float m[16];
    if (tid < PTHREADS) {
        #pragma unroll
        for (int j = 0; j < 16; j++)
            m[j] = (row_g == c0 + j) ? 1.0f : 0.0f;
    }
    const uint32_t part2_base = smem_u32(&sm.part2[0][0]);
    const uint32_t mbar_base  = smem_u32(&sm.mbar[0]);

    // ---- S persistent state (replicated on both CTAs; 4 rows per lane) ----
    const int lane = tid - PTHREADS;
    const int i0   = lane * 4;
    float w0 = 0.f, w1 = 0.f, w2 = 0.f, w3 = 0.f;
    float pp0 = 0.f, pp1 = 0.f, pp2 = 0.f, pp3 = 0.f;
    float pv0 = 0.f, pv1 = 0.f, pv2 = 0.f, pv3 = 0.f;
    float cp0 = 0.f, cv0 = 0.f, cp1 = 0.f, cv1 = 0.f;

    #pragma unroll 1
    for (int t = 0; t < NBLK; t++) {
        const int k    = 2 * t;
        const int buf  = t & 1;        // pc/vc/au/bu ring (local, bar-ordered)
        const int cur4 = t & 3;        // part2 slot consumed by S this iter
        const int nb4  = (t + 1) & 3;  // part2 slot produced by P this iter
        if (tid < PTHREADS) {
            // ===== P: rank-2 update (prev block) fused with 2 matvecs =====
            const float nau = -sm.au[buf][row_g];
            const float nbu = -sm.bu[buf][row_g];
            float acc0 = 0.f, acc1 = 0.f;
            #pragma unroll
            for (int q = 0; q < 4; q++) {
                const float4 pc4 = *reinterpret_cast<const float4*>(&sm.pc[buf][c0 + 4*q]);
                const float4 vc4 = *reinterpret_cast<const float4*>(&sm.vc[buf][c0 + 4*q]);
                const float4 x24 = *reinterpret_cast<const float4*>(&sm.xs[k + 2][c0 + 4*q]);
                const float4 x34 = *reinterpret_cast<const float4*>(&sm.xs[k + 3][c0 + 4*q]);
                float mv;
                mv = m[4*q+0]; mv = fmaf(nau, pc4.x, mv); mv = fmaf(nbu, vc4.x, mv);
                m[4*q+0] = mv; acc0 = fmaf(mv, x24.x, acc0); acc1 = fmaf(mv, x34.x, acc1);
                mv = m[4*q+1]; mv = fmaf(nau, pc4.y, mv); mv = fmaf(nbu, vc4.y, mv);
                m[4*q+1] = mv; acc0 = fmaf(mv, x24.y, acc0); acc1 = fmaf(mv, x34.y, acc1);
                mv = m[4*q+2]; mv = fmaf(nau, pc4.z, mv); mv = fmaf(nbu, vc4.z, mv);
                m[4*q+2] = mv; acc0 = fmaf(mv, x24.z, acc0); acc1 = fmaf(mv, x34.z, acc1);
                mv = m[4*q+3]; mv = fmaf(nau, pc4.w, mv); mv = fmaf(nbu, vc4.w, mv);
                m[4*q+3] = mv; acc0 = fmaf(mv, x24.w, acc0); acc1 = fmaf(mv, x34.w, acc1);
            }
            // reduce the 8 col-groups of this row (lanes 8j..8j+7)
            #pragma unroll
            for (int off = 1; off < 8; off <<= 1) {
                acc0 += __shfl_xor_sync(0xffffffffu, acc0, off);
                acc1 += __shfl_xor_sync(0xffffffffu, acc1, off);
            }
            if (cg == 0) {
                sm.part2[nb4][row_g] = make_float2(acc0, acc1);   // local copy
                unsigned long long pk =
                    ((unsigned long long)__float_as_uint(acc1) << 32) |
                    __float_as_uint(acc0);
                sts_remote_u64(part2_base + (uint32_t)(nb4 * DIM + row_g) * 8u,
                               pk, peer);                          // peer copy
            }
            __syncwarp();
            if ((tid & 31) == 0)
                mbar_arrive_remote(mbar_base + (uint32_t)nb4 * 8u, peer);
        } else {
            // ===== S (replicated): wait remote half, correct, reduce, math =====
            if (t > 0) {
                const uint32_t parity =
                    (uint32_t)(((t >> 2) & 1) ^ ((t & 3) == 0 ? 1 : 0));
                mbar_wait_cluster(mbar_base + (uint32_t)cur4 * 8u, parity);
            }
            const float4 ra = *reinterpret_cast<const float4*>(&sm.part2[cur4][i0]);
            const float4 rb = *reinterpret_cast<const float4*>(&sm.part2[cur4][i0 + 2]);
            const float p0 = ra.x - cp0 * pp0 - cv0 * pv0;
            const float q0 = ra.y - cp1 * pp0 - cv1 * pv0;
            const float p1 = ra.z - cp0 * pp1 - cv0 * pv1;
            const float q1 = ra.w - cp1 * pp1 - cv1 * pv1;
            const float p2 = rb.x - cp0 * pp2 - cv0 * pv2;
            const float q2 = rb.y - cp1 * pp2 - cv1 * pv2;
            const float p3 = rb.z - cp0 * pp3 - cv0 * pv3;
            const float q3 = rb.w - cp1 * pp3 - cv1 * pv3;

            const float4 xk  = *reinterpret_cast<const float4*>(&sm.xs[k][i0]);
            const float4 xk1 = *reinterpret_cast<const float4*>(&sm.xs[k + 1][i0]);
            const float4 xk2 = *reinterpret_cast<const float4*>(&sm.xs[k + 2][i0]);
            const float4 xk3 = *reinterpret_cast<const float4*>(&sm.xs[k + 3][i0]);

            float s1v = (xk.x  * p0 + xk.y  * p1) + (xk.z  * p2 + xk.w  * p3);
            float cS  = (xk.x  * q0 + xk.y  * q1) + (xk.z  * q2 + xk.w  * q3);
            float s2  = (xk1.x * q0 + xk1.y * q1) + (xk1.z * q2 + xk1.w * q3);
            float ew0 = (xk.x  * w0 + xk.y  * w1) + (xk.z  * w2 + xk.w  * w3);
            float ew1 = (xk1.x * w0 + xk1.y * w1) + (xk1.z * w2 + xk1.w * w3);
            float ew2 = (xk2.x * w0 + xk2.y * w1) + (xk2.z * w2 + xk2.w * w3);
            float d1  = (xk2.x * p0 + xk2.y * p1) + (xk2.z * p2 + xk2.w * p3);
            float d2  = (xk2.x * q0 + xk2.y * q1) + (xk2.z * q2 + xk2.w * q3);
            float d3  = (xk3.x * p0 + xk3.y * p1) + (xk3.z * p2 + xk3.w * p3);
            float d4  = (xk3.x * q0 + xk3.y * q1) + (xk3.z * q2 + xk3.w * q3);

            #pragma unroll
            for (int off = 16; off > 0; off >>= 1) {
                s1v += __shfl_xor_sync(0xffffffffu, s1v, off);
                cS  += __shfl_xor_sync(0xffffffffu, cS,  off);
                s2  += __shfl_xor_sync(0xffffffffu, s2,  off);
                ew0 += __shfl_xor_sync(0xffffffffu, ew0, off);
                ew1 += __shfl_xor_sync(0xffffffffu, ew1, off);
                ew2 += __shfl_xor_sync(0xffffffffu, ew2, off);
                d1  += __shfl_xor_sync(0xffffffffu, d1,  off);
                d2  += __shfl_xor_sync(0xffffffffu, d2,  off);
                d3  += __shfl_xor_sync(0xffffffffu, d3,  off);
                d4  += __shfl_xor_sync(0xffffffffu, d4,  off);
            }

            const float inv1  = 1.0f / (1.0f + s1v);
            const float coef0 = (sm.ts[k] - ew0) * inv1;
            const float cc    = cS * inv1;
            const float t2    = s2 - cS * cc;
            const float inv2  = 1.0f / (1.0f + t2);
            const float pred1 = fmaf(coef0, cS, ew1);
            const float coef1 = (sm.ts[k + 1] - pred1) * inv2;
            const float pred2 = ew2 + coef0 * d1 + coef1 * (d2 - cc * d1);

            const float nv0 = q0 - cc * p0, nv1 = q1 - cc * p1;
            const float nv2 = q2 - cc * p2, nv3 = q3 - cc * p3;
            w0 += coef0 * p0 + coef1 * nv0;
            w1 += coef0 * p1 + coef1 * nv1;
            w2 += coef0 * p2 + coef1 * nv2;
            w3 += coef0 * p3 + coef1 * nv3;

            const int nbs = buf ^ 1;
            *reinterpret_cast<float4*>(&sm.pc[nbs][i0]) = make_float4(p0, p1, p2, p3);
            *reinterpret_cast<float4*>(&sm.vc[nbs][i0]) = make_float4(nv0, nv1, nv2, nv3);
            *reinterpret_cast<float4*>(&sm.au[nbs][i0]) =
                make_float4(inv1 * p0, inv1 * p1, inv1 * p2, inv1 * p3);
            *reinterpret_cast<float4*>(&sm.bu[nbs][i0]) =
                make_float4(inv2 * nv0, inv2 * nv1, inv2 * nv2, inv2 * nv3);

            if (lane == 0 && half == 0) {
                out[(size_t)b * NPTS + k + 1] = pred1;
                if (k + 2 < NPTS) out[(size_t)b * NPTS + k + 2] = pred2;
            }

            pp0 = p0; pp1 = p1; pp2 = p2; pp3 = p3;
            pv0 = nv0; pv1 = nv1; pv2 = nv2; pv3 = nv3;
            cp0 = inv1 * d1;  cv0 = inv2 * (d2 - cc * d1);
            cp1 = inv1 * d3;  cv1 = inv2 * (d4 - cc * d3);
        }
        __syncthreads();
    }

    // keep SMEM alive until peer's final remote stores/arrives are done
    asm volatile("barrier.cluster.arrive.aligned;" ::: "memory");
    asm volatile("barrier.cluster.wait.aligned;" ::: "memory");
}

extern "C" void kernel_launch(void* const* d_in, const int* in_sizes, int n_in,
                              void* d_out, int out_size)
{
    const float* data    = (const float*)d_in[0];   // [32, 256, 128] f32
    const float* targets = (const float*)d_in[1];   // [32, 256]      f32
    float* out = (float*)d_out;                     // [32, 256]      f32

    const size_t smem_bytes = sizeof(SMLayout);
    cudaFuncSetAttribute(ridge_rls_cl_kernel,
                         cudaFuncAttributeMaxDynamicSharedMemorySize,
                         (int)smem_bytes);
    ridge_rls_cl_kernel<<<BATCH * 2, TOT, smem_bytes>>>(data, targets, out);
}

// round 9
// speedup vs baseline: 2.5075x; 2.5075x over previous
#include <cuda_runtime.h>
#include <cstdint>
#include <cstddef>

// Ridge_51178830299316 — rank-2 blocked RLS (Woodbury), round 9.
// = round-3 champion (149.3us) with the P-phase inner loop restructured as an
// explicit 2-stage software pipeline (loads of stage s+1 interleaved with the
// FMA2s of stage s, __syncwarp() stage fences) to break the post-barrier
// lockstep that serialized the LSU burst (~544 cyc) and FMA burst (~512 cyc).
// S warp and all algebra are byte-identical to round 3.

#define BATCH 32
#define NPTS  256
#define DIM   128
#define PTHREADS 512
#define TOT   544
#define NBLK  128            // blocks of 2 steps (x padded with 2 zero rows)

#define FMA2(d, a, bb, c) \
    asm("fma.rn.f32x2 %0, %1, %2, %3;" : "=l"(d) : "l"(a), "l"(bb), "l"(c))

struct SMLayout {
    float xs[NPTS + 2][DIM];     // padded with 2 zero rows
    float ts[NPTS];
    float part[2][2][DIM][4];    // [buf][matvec 0/1][row][cb]
    float pc[2][DIM];            // column-side p
    float vc[2][DIM];            // column-side v
    float au[2][DIM];            // inv1 * p  (row-side)
    float bu[2][DIM];            // inv2 * v  (row-side)
};

__device__ __forceinline__ float ull_lo(unsigned long long x) {
    return __uint_as_float((unsigned)x);
}
__device__ __forceinline__ float ull_hi(unsigned long long x) {
    return __uint_as_float((unsigned)(x >> 32));
}
__device__ __forceinline__ unsigned long long pack2(float f) {
    unsigned long long r;
    asm("mov.b64 %0, {%1, %1};" : "=l"(r) : "r"(__float_as_uint(f)));
    return r;
}

__global__ void __launch_bounds__(TOT, 1)
ridge_rls2p_kernel(const float* __restrict__ data,
                   const float* __restrict__ targets,
                   float* __restrict__ out)
{
    extern __shared__ char smem_raw[];
    SMLayout& sm = *reinterpret_cast<SMLayout*>(smem_raw);
    const int tid = threadIdx.x;
    const int b   = blockIdx.x;

    // ---- Stage inputs ----
    {
        const float4* src = reinterpret_cast<const float4*>(data + (size_t)b * NPTS * DIM);
        float4* dst = reinterpret_cast<float4*>(&sm.xs[0][0]);
        for (int idx = tid; idx < NPTS * DIM / 4; idx += TOT)
            dst[idx] = src[idx];
        if (tid < 2 * DIM / 4)
            reinterpret_cast<float4*>(&sm.xs[NPTS][0])[tid] =
                make_float4(0.f, 0.f, 0.f, 0.f);
        if (tid < NPTS / 4)
            reinterpret_cast<float4*>(sm.ts)[tid] =
                reinterpret_cast<const float4*>(targets + (size_t)b * NPTS)[tid];
    }
    __syncthreads();

    // ---- Prologue: raw matvecs of block 0 are I*x_0, I*x_1 ----
    if (tid < DIM) {
        *reinterpret_cast<float4*>(sm.part[0][0][tid]) =
            make_float4(sm.xs[0][tid], 0.f, 0.f, 0.f);
        *reinterpret_cast<float4*>(sm.part[0][1][tid]) =
            make_float4(sm.xs[1][tid], 0.f, 0.f, 0.f);
        sm.pc[0][tid] = 0.f;  sm.vc[0][tid] = 0.f;   // block -1 update = 0
        sm.au[0][tid] = 0.f;  sm.bu[0][tid] = 0.f;
    }
    if (tid == 0) out[(size_t)b * NPTS] = 0.f;
    __syncthreads();

    // ---- P persistent state: M = I as packed f32x2 ----
    const int row = tid & 127;
    const int cb  = (tid >> 7) & 3;
    unsigned long long m[16];
    if (tid < PTHREADS) {
        #pragma unroll
        for (int j = 0; j < 16; j++) {
            unsigned lo = (cb * 32 + 2 * j     == row) ? 0x3f800000u : 0u;
            unsigned hi = (cb * 32 + 2 * j + 1 == row) ? 0x3f800000u : 0u;
            m[j] = ((unsigned long long)hi << 32) | lo;
        }
    }

    // ---- S persistent state (4 rows per lane) ----
    const int lane = tid - PTHREADS;
    const int i0   = lane * 4;
    float w0 = 0.f, w1 = 0.f, w2 = 0.f, w3 = 0.f;
    float pp0 = 0.f, pp1 = 0.f, pp2 = 0.f, pp3 = 0.f;
    float pv0 = 0.f, pv1 = 0.f, pv2 = 0.f, pv3 = 0.f;
    float cp0 = 0.f, cv0 = 0.f, cp1 = 0.f, cv1 = 0.f;

    int buf = 0;
    #pragma unroll 1
    for (int t = 0; t < NBLK; t++) {
        const int k = 2 * t;
        if (tid < PTHREADS) {
            // ===== P: rank-2 update fused with 2 matvecs, 2-stage pipeline =====
            const unsigned long long nn1 = pack2(-sm.au[buf][row]);
            const unsigned long long nn2 = pack2(-sm.bu[buf][row]);
            const ulonglong2* pcp =
                reinterpret_cast<const ulonglong2*>(&sm.pc[buf][cb * 32]);
            const ulonglong2* vcp =
                reinterpret_cast<const ulonglong2*>(&sm.vc[buf][cb * 32]);
            const ulonglong2* x0p =
                reinterpret_cast<const ulonglong2*>(&sm.xs[k + 2][cb * 32]);
            const ulonglong2* x1p =
                reinterpret_cast<const ulonglong2*>(&sm.xs[k + 3][cb * 32]);

            unsigned long long rA0 = 0ull, rB0 = 0ull, rA1 = 0ull, rB1 = 0ull;

            // stage 0 preload (q = 0,1)
            ulonglong2 P0 = pcp[0], V0 = vcp[0], X0 = x0p[0], Y0 = x1p[0];
            ulonglong2 P1 = pcp[1], V1 = vcp[1], X1 = x0p[1], Y1 = x1p[1];

            #pragma unroll
            for (int s = 0; s < 4; s++) {
                ulonglong2 nP0 = P0, nV0 = V0, nX0 = X0, nY0 = Y0;
                ulonglong2 nP1 = P1, nV1 = V1, nX1 = X1, nY1 = Y1;
                if (s < 3) {   // compile-time resolved: no loads in last stage
                    nP0 = pcp[2*s+2]; nV0 = vcp[2*s+2];
                    nX0 = x0p[2*s+2]; nY0 = x1p[2*s+2];
                    nP1 = pcp[2*s+3]; nV1 = vcp[2*s+3];
                    nX1 = x0p[2*s+3]; nY1 = x1p[2*s+3];
                }
                {
                    const int q = 2 * s;
                    FMA2(m[2*q],   nn1, P0.x, m[2*q]);
                    FMA2(m[2*q],   nn2, V0.x, m[2*q]);
                    FMA2(rA0, m[2*q], X0.x, rA0);
                    FMA2(rA1, m[2*q], Y0.x, rA1);
                    FMA2(m[2*q+1], nn1, P0.y, m[2*q+1]);
                    FMA2(m[2*q+1], nn2, V0.y, m[2*q+1]);
                    FMA2(rB0, m[2*q+1], X0.y, rB0);
                    FMA2(rB1, m[2*q+1], Y0.y, rB1);
                }
                {
                    const int q = 2 * s + 1;
                    FMA2(m[2*q],   nn1, P1.x, m[2*q]);
                    FMA2(m[2*q],   nn2, V1.x, m[2*q]);
                    FMA2(rA0, m[2*q], X1.x, rA0);
                    FMA2(rA1, m[2*q], Y1.x, rA1);
                    FMA2(m[2*q+1], nn1, P1.y, m[2*q+1]);
                    FMA2(m[2*q+1], nn2, V1.y, m[2*q+1]);
                    FMA2(rB0, m[2*q+1], X1.y, rB0);
                    FMA2(rB1, m[2*q+1], Y1.y, rB1);
                }
                __syncwarp(0xffffffffu);   // stage fence: bounds load hoisting
                P0 = nP0; V0 = nV0; X0 = nX0; Y0 = nY0;
                P1 = nP1; V1 = nV1; X1 = nX1; Y1 = nY1;
            }
            sm.part[buf ^ 1][0][row][cb] =
                (ull_lo(rA0) + ull_hi(rA0)) + (ull_lo(rB0) + ull_hi(rB0));
            sm.part[buf ^ 1][1][row][cb] =
                (ull_lo(rA1) + ull_hi(rA1)) + (ull_lo(rB1) + ull_hi(rB1));
        } else {
            // ===== S: correct staleness, 10-value reduce, scalar math =====
            float p0, p1, p2, p3, q0, q1, q2, q3;
            {
                const float4 r0 = *reinterpret_cast<const float4*>(sm.part[buf][0][i0 + 0]);
                const float4 r1 = *reinterpret_cast<const float4*>(sm.part[buf][0][i0 + 1]);
                const float4 r2 = *reinterpret_cast<const float4*>(sm.part[buf][0][i0 + 2]);
                const float4 r3 = *reinterpret_cast<const float4*>(sm.part[buf][0][i0 + 3]);
                p0 = (r0.x + r0.y) + (r0.z + r0.w) - cp0 * pp0 - cv0 * pv0;
                p1 = (r1.x + r1.y) + (r1.z + r1.w) - cp0 * pp1 - cv0 * pv1;
                p2 = (r2.x + r2.y) + (r2.z + r2.w) - cp0 * pp2 - cv0 * pv2;
                p3 = (r3.x + r3.y) + (r3.z + r3.w) - cp0 * pp3 - cv0 * pv3;
            }
            {
                const float4 r0 = *reinterpret_cast<const float4*>(sm.part[buf][1][i0 + 0]);
                const float4 r1 = *reinterpret_cast<const float4*>(sm.part[buf][1][i0 + 1]);
                const float4 r2 = *reinterpret_cast<const float4*>(sm.part[buf][1][i0 + 2]);
                const float4 r3 = *reinterpret_cast<const float4*>(sm.part[buf][1][i0 + 3]);
                q0 = (r0.x + r0.y) + (r0.z + r0.w) - cp1 * pp0 - cv1 * pv0;
                q1 = (r1.x + r1.y) + (r1.z + r1.w) - cp1 * pp1 - cv1 * pv1;
                q2 = (r2.x + r2.y) + (r2.z + r2.w) - cp1 * pp2 - cv1 * pv2;
                q3 = (r3.x + r3.y) + (r3.z + r3.w) - cp1 * pp3 - cv1 * pv3;
            }
            const float4 xk  = *reinterpret_cast<const float4*>(&sm.xs[k][i0]);
            const float4 xk1 = *reinterpret_cast<const float4*>(&sm.xs[k + 1][i0]);
            const float4 xk2 = *reinterpret_cast<const float4*>(&sm.xs[k + 2][i0]);
            const float4 xk3 = *reinterpret_cast<const float4*>(&sm.xs[k + 3][i0]);

            float s1  = (xk.x  * p0 + xk.y  * p1) + (xk.z  * p2 + xk.w  * p3);
            float cS  = (xk.x  * q0 + xk.y  * q1) + (xk.z  * q2 + xk.w  * q3);
            float s2  = (xk1.x * q0 + xk1.y * q1) + (xk1.z * q2 + xk1.w * q3);
            float ew0 = (xk.x  * w0 + xk.y  * w1) + (xk.z  * w2 + xk.w  * w3);
            float ew1 = (xk1.x * w0 + xk1.y * w1) + (xk1.z * w2 + xk1.w * w3);
            float ew2 = (xk2.x * w0 + xk2.y * w1) + (xk2.z * w2 + xk2.w * w3);
            float d1  = (xk2.x * p0 + xk2.y * p1) + (xk2.z * p2 + xk2.w * p3);
            float d2  = (xk2.x * q0 + xk2.y * q1) + (xk2.z * q2 + xk2.w * q3);
            float d3  = (xk3.x * p0 + xk3.y * p1) + (xk3.z * p2 + xk3.w * p3);
            float d4  = (xk3.x * q0 + xk3.y * q1) + (xk3.z * q2 + xk3.w * q3);

            #pragma unroll
            for (int off = 16; off > 0; off >>= 1) {
                s1  += __shfl_xor_sync(0xffffffffu, s1,  off);
                cS  += __shfl_xor_sync(0xffffffffu, cS,  off);
                s2  += __shfl_xor_sync(0xffffffffu, s2,  off);
                ew0 += __shfl_xor_sync(0xffffffffu, ew0, off);
                ew1 += __shfl_xor_sync(0xffffffffu, ew1, off);
                ew2 += __shfl_xor_sync(0xffffffffu, ew2, off);
                d1  += __shfl_xor_sync(0xffffffffu, d1,  off);
                d2  += __shfl_xor_sync(0xffffffffu, d2,  off);
                d3  += __shfl_xor_sync(0xffffffffu, d3,  off);
                d4  += __shfl_xor_sync(0xffffffffu, d4,  off);
            }

            const float inv1  = 1.0f / (1.0f + s1);
            const float coef0 = (sm.ts[k] - ew0) * inv1;
            const float cc    = cS * inv1;
            const float t2    = s2 - cS * cc;
            const float inv2  = 1.0f / (1.0f + t2);
            const float pred1 = fmaf(coef0, cS, ew1);
            const float coef1 = (sm.ts[k + 1] - pred1) * inv2;
            const float pred2 = ew2 + coef0 * d1 + coef1 * (d2 - cc * d1);

            const float nv0 = q0 - cc * p0, nv1 = q1 - cc * p1;
            const float nv2 = q2 - cc * p2, nv3 = q3 - cc * p3;
            w0 += coef0 * p0 + coef1 * nv0;
            w1 += coef0 * p1 + coef1 * nv1;
            w2 += coef0 * p2 + coef1 * nv2;
            w3 += coef0 * p3 + coef1 * nv3;

            const int nb = buf ^ 1;
            *reinterpret_cast<float4*>(&sm.pc[nb][i0]) = make_float4(p0, p1, p2, p3);
            *reinterpret_cast<float4*>(&sm.vc[nb][i0]) = make_float4(nv0, nv1, nv2, nv3);
            *reinterpret_cast<float4*>(&sm.au[nb][i0]) =
                make_float4(inv1 * p0, inv1 * p1, inv1 * p2, inv1 * p3);
            *reinterpret_cast<float4*>(&sm.bu[nb][i0]) =
                make_float4(inv2 * nv0, inv2 * nv1, inv2 * nv2, inv2 * nv3);

            if (lane == 0) {
                out[(size_t)b * NPTS + k + 1] = pred1;
                if (k + 2 < NPTS) out[(size_t)b * NPTS + k + 2] = pred2;
            }

            pp0 = p0; pp1 = p1; pp2 = p2; pp3 = p3;
            pv0 = nv0; pv1 = nv1; pv2 = nv2; pv3 = nv3;
            cp0 = inv1 * d1;  cv0 = inv2 * (d2 - cc * d1);
            cp1 = inv1 * d3;  cv1 = inv2 * (d4 - cc * d3);
        }
        __syncthreads();
        buf ^= 1;
    }
}

extern "C" void kernel_launch(void* const* d_in, const int* in_sizes, int n_in,
                              void* d_out, int out_size)
{
    const float* data    = (const float*)d_in[0];   // [32, 256, 128] f32
    const float* targets = (const float*)d_in[1];   // [32, 256]      f32
    float* out = (float*)d_out;                     // [32, 256]      f32

    const size_t smem_bytes = sizeof(SMLayout);
    cudaFuncSetAttribute(ridge_rls2p_kernel,
                         cudaFuncAttributeMaxDynamicSharedMemorySize,
                         (int)smem_bytes);
    ridge_rls2p_kernel<<<BATCH, TOT, smem_bytes>>>(data, targets, out);
}

// round 12
// speedup vs baseline: 3.8760x; 1.5458x over previous
#include <cuda_runtime.h>
#include <cstdint>
#include <cstddef>

// Ridge_51178830299316 — dual (kernel-space) formulation, round 12
// (third submission; rounds 10/11 hit broker container failures before run).
//
// pred_{k+1} = g^T (G_k + I)^{-1} y_{1:k},  G = X X^T  (push-through identity).
// One Cholesky of A = G + I per batch serves ALL prefixes (leading-block
// property). Fused forward substitution: maintain u = y - pred; z_j = u_j /
// L[jj] at column j; u_r -= L[r,j] z_j. Final predictions = y - u_final
// (pred[0] = 0 automatically).
//
// K1: Gram. grid = 32 batches x 36 lower tiles (32x32). smem-staged X rows,
//     2x2 register tiles, writes packed-lower (4-aligned padded rows) + I.
// K2: fused Cholesky+forward-sub. 1 CTA/batch, 512 threads, A in smem.
//     8 panels of 32: (A) warp0 diag-block Cholesky via shfl+colbuf,
//     (B) thread-per-row triangular solve -> LT[32][256] scratch + u update,
//     (C) register-tiled (8x8/thread) rank-32 trailing update (pure FMA).

#define NPTS   256
#define DIM    128
#define BATCH  32
#define NPANEL 8
#define K2T    512
#define APACK_SIZE 33280   // sum of 4-aligned row lengths (= base(256))

// base(r) = sum_{s<r} align4(s+1) ; rows 16B-aligned, no overlap.
__host__ __device__ __forceinline__ int rowbase(int r) {
    const int q = r >> 2, rem = r & 3;
    return 8 * q * (q - 1) + 4 * rem * q + 4 * r;
}

__device__ float g_gram[BATCH][APACK_SIZE];

// ============================ K1: Gram ====================================
__global__ void __launch_bounds__(256) gram_kernel(const float* __restrict__ data)
{
    const int bid = blockIdx.x;
    const int b = bid / 36, t36 = bid % 36;
    int ti = 0;
    while ((ti + 1) * (ti + 2) / 2 <= t36) ++ti;   // ti >= tj decode (<=8 iters)
    const int tj = t36 - ti * (ti + 1) / 2;

    __shared__ float Xi[32][132];
    __shared__ float Xj[32][132];

    const float* Xb = data + (size_t)b * NPTS * DIM;
    const int tid = threadIdx.x;
    for (int q = tid; q < 1024; q += 256) {           // 32 rows x 32 float4
        const int r = q >> 5, c4 = q & 31;
        *reinterpret_cast<float4*>(&Xi[r][c4 * 4]) =
            reinterpret_cast<const float4*>(Xb + (size_t)(ti * 32 + r) * DIM)[c4];
        *reinterpret_cast<float4*>(&Xj[r][c4 * 4]) =
            reinterpret_cast<const float4*>(Xb + (size_t)(tj * 32 + r) * DIM)[c4];
    }
    __syncthreads();

    const int ty = tid >> 4, tx = tid & 15;
    const int r0 = 2 * ty, c0 = 2 * tx;
    float a00 = 0.f, a01 = 0.f, a10 = 0.f, a11 = 0.f;
    #pragma unroll 8
    for (int k4 = 0; k4 < 32; ++k4) {
        const float4 xi0 = *reinterpret_cast<const float4*>(&Xi[r0][k4 * 4]);
        const float4 xi1 = *reinterpret_cast<const float4*>(&Xi[r0 + 1][k4 * 4]);
        const float4 xj0 = *reinterpret_cast<const float4*>(&Xj[c0][k4 * 4]);
        const float4 xj1 = *reinterpret_cast<const float4*>(&Xj[c0 + 1][k4 * 4]);
        a00 += xi0.x*xj0.x + xi0.y*xj0.y + xi0.z*xj0.z + xi0.w*xj0.w;
        a01 += xi0.x*xj1.x + xi0.y*xj1.y + xi0.z*xj1.z + xi0.w*xj1.w;
        a10 += xi1.x*xj0.x + xi1.y*xj0.y + xi1.z*xj0.z + xi1.w*xj0.w;
        a11 += xi1.x*xj1.x + xi1.y*xj1.y + xi1.z*xj1.z + xi1.w*xj1.w;
    }
    const int gr0 = ti * 32 + r0, gc0 = tj * 32 + c0;
    float* gg = g_gram[b];
    if (gr0 >= gc0)         gg[rowbase(gr0)     + gc0]     = a00 + (gr0     == gc0     ? 1.f : 0.f);
    if (gr0 >= gc0 + 1)     gg[rowbase(gr0)     + gc0 + 1] = a01 + (gr0     == gc0 + 1 ? 1.f : 0.f);
    if (gr0 + 1 >= gc0)     gg[rowbase(gr0 + 1) + gc0]     = a10 + (gr0 + 1 == gc0     ? 1.f : 0.f);
    if (gr0 + 1 >= gc0 + 1) gg[rowbase(gr0 + 1) + gc0 + 1] = a11 + (gr0 + 1 == gc0 + 1 ? 1.f : 0.f);
}

// ==================== K2: fused Cholesky + forward sub ====================
struct K2Smem {
    float A[APACK_SIZE];     // packed lower, 4-aligned rows (133120 B)
    float u[NPTS];           // residual y - pred
    float z[32];
    float invD[32];
    float D[32][32];         // current panel diagonal block L
    float LT[32][256];       // current panel L, transposed [p][row]
    float colbuf[32];
};

__global__ void __launch_bounds__(K2T, 1)
chol_kernel(const float* __restrict__ targets, float* __restrict__ out)
{
    extern __shared__ char smraw[];
    K2Smem& sm = *reinterpret_cast<K2Smem*>(smraw);
    const int b = blockIdx.x, tid = threadIdx.x;

    {
        const float4* src = reinterpret_cast<const float4*>(g_gram[b]);
        float4* dst = reinterpret_cast<float4*>(sm.A);
        for (int i = tid; i < APACK_SIZE / 4; i += K2T) dst[i] = src[i];
    }
    if (tid < NPTS) sm.u[tid] = targets[(size_t)b * NPTS + tid];
    __syncthreads();

    #pragma unroll 1
    for (int k = 0; k < NPANEL; ++k) {
        const int P = 32 * k;

        // -------- Phase A: diagonal 32x32 Cholesky (warp 0, shfl) --------
        if (tid < 32) {
            const int rp = tid, gr = P + rp, rb = rowbase(gr);
            float arow[32];
            #pragma unroll
            for (int c = 0; c < 32; ++c) arow[c] = sm.A[rb + P + c];  // c>rp garbage, unused
            float ur = sm.u[gr];
            #pragma unroll
            for (int c = 0; c < 32; ++c) {
                const float d  = __shfl_sync(0xffffffffu, arow[c], c);
                const float uc = __shfl_sync(0xffffffffu, ur, c);
                const float rs = rsqrtf(d);
                const float zc = uc * rs;
                const float lrc = (rp > c) ? arow[c] * rs : 0.f;
                if (rp == c) { arow[c] = d * rs; sm.z[c] = zc; sm.invD[c] = rs; }
                if (rp > c)  { arow[c] = lrc; ur -= lrc * zc; }
                sm.colbuf[rp] = lrc;
                __syncwarp();
                float cb[32];
                #pragma unroll
                for (int q = 0; q < 8; ++q)
                    *reinterpret_cast<float4*>(&cb[4 * q]) =
                        *reinterpret_cast<const float4*>(&sm.colbuf[4 * q]);
                #pragma unroll
                for (int j = 0; j < 32; ++j)
                    if (j > c) arow[j] -= lrc * cb[j];
                __syncwarp();
            }
            sm.u[gr] = ur;
            #pragma unroll
            for (int q = 0; q < 8; ++q)
                *reinterpret_cast<float4*>(&sm.D[rp][4 * q]) =
                    *reinterpret_cast<const float4*>(&arow[4 * q]);
        }
        __syncthreads();

        // -------- Phase B: panel rows triangular solve + u update --------
        const int R = NPTS - P - 32;
        if (tid < R) {
            const int gr = P + 32 + tid, rb = rowbase(gr);
            float Lr[32], zreg[32];
            #pragma unroll
            for (int q = 0; q < 8; ++q)
                *reinterpret_cast<float4*>(&zreg[4 * q]) =
                    *reinterpret_cast<const float4*>(&sm.z[4 * q]);
            #pragma unroll
            for (int c = 0; c < 32; ++c) {
                float acc = sm.A[rb + P + c];
                #pragma unroll
                for (int p = 0; p < 32; ++p)
                    if (p < c) acc -= Lr[p] * sm.D[c][p];
                Lr[c] = acc * sm.invD[c];
            }
            float du = 0.f;
            #pragma unroll
            for (int c = 0; c < 32; ++c) du += Lr[c] * zreg[c];
            sm.u[gr] -= du;
            #pragma unroll
            for (int c = 0; c < 32; ++c) sm.LT[c][gr] = Lr[c];
        }
        __syncthreads();

        // -------- Phase C: rank-32 trailing update (8x8 register tiles) --
        const int c0t = 4 * (k + 1);
        const int mrem = 32 - c0t;
        const int Tact = mrem * (mrem + 1) / 2;
        for (int a = tid; a < Tact; a += K2T) {
            int t = (int)(0.5f * (__fsqrt_rn(8.f * a + 1.f) - 1.f));
            while ((t + 1) * (t + 2) / 2 <= a) ++t;
            while (t * (t + 1) / 2 > a) --t;
            const int tc = 31 - t;
            const int tr = 31 - (a - t * (t + 1) / 2);
            const int r0 = 8 * tr, cc0 = 8 * tc;

            float acc[8][8];
            int rbs[8];
            #pragma unroll
            for (int i = 0; i < 8; ++i) {
                rbs[i] = rowbase(r0 + i);
                const float4 v0 = *reinterpret_cast<const float4*>(&sm.A[rbs[i] + cc0]);
                const float4 v1 = *reinterpret_cast<const float4*>(&sm.A[rbs[i] + cc0 + 4]);
                acc[i][0] = v0.x; acc[i][1] = v0.y; acc[i][2] = v0.z; acc[i][3] = v0.w;
                acc[i][4] = v1.x; acc[i][5] = v1.y; acc[i][6] = v1.z; acc[i][7] = v1.w;
            }
            #pragma unroll 4
            for (int p = 0; p < 32; ++p) {
                const float4 lr0 = *reinterpret_cast<const float4*>(&sm.LT[p][r0]);
                const float4 lr1 = *reinterpret_cast<const float4*>(&sm.LT[p][r0 + 4]);
                const float4 lc0 = *reinterpret_cast<const float4*>(&sm.LT[p][cc0]);
                const float4 lc1 = *reinterpret_cast<const float4*>(&sm.LT[p][cc0 + 4]);
                const float lr[8] = {lr0.x, lr0.y, lr0.z, lr0.w, lr1.x, lr1.y, lr1.z, lr1.w};
                const float lc[8] = {lc0.x, lc0.y, lc0.z, lc0.w, lc1.x, lc1.y, lc1.z, lc1.w};
                #pragma unroll
                for (int i = 0; i < 8; ++i)
                    #pragma unroll
                    for (int j = 0; j < 8; ++j)
                        acc[i][j] -= lr[i] * lc[j];
            }
            if (tr != tc) {
                #pragma unroll
                for (int i = 0; i < 8; ++i) {
                    *reinterpret_cast<float4*>(&sm.A[rbs[i] + cc0]) =
                        make_float4(acc[i][0], acc[i][1], acc[i][2], acc[i][3]);
                    *reinterpret_cast<float4*>(&sm.A[rbs[i] + cc0 + 4]) =
                        make_float4(acc[i][4], acc[i][5], acc[i][6], acc[i][7]);
                }
            } else {
                #pragma unroll
                for (int i = 0; i < 8; ++i)
                    #pragma unroll
                    for (int j = 0; j < 8; ++j)
                        if (j <= i) sm.A[rbs[i] + cc0 + j] = acc[i][j];
            }
        }
        __syncthreads();
    }

    for (int j = tid; j < NPTS; j += K2T)
        out[(size_t)b * NPTS + j] = targets[(size_t)b * NPTS + j] - sm.u[j];
}

extern "C" void kernel_launch(void* const* d_in, const int* in_sizes, int n_in,
                              void* d_out, int out_size)
{
    const float* data    = (const float*)d_in[0];   // [32, 256, 128] f32
    const float* targets = (const float*)d_in[1];   // [32, 256]      f32
    float* out = (float*)d_out;                     // [32, 256]      f32

    gram_kernel<<<BATCH * 36, 256>>>(data);

    const size_t smem_bytes = sizeof(K2Smem);
    cudaFuncSetAttribute(chol_kernel,
                         cudaFuncAttributeMaxDynamicSharedMemorySize,
                         (int)smem_bytes);
    chol_kernel<<<BATCH, K2T, smem_bytes>>>(targets, out);
}